// round 2
// baseline (speedup 1.0000x reference)
#include <cuda_runtime.h>

#define Bh  256
#define Nh  128
#define BNh 32768
#define NEh 524288
#define Fh  8
#define Hh  4
#define H1h 32
#define H2h 16
#define H3h 512
#define LATh 128
#define Ch  32

// ---------------- scratch (static device globals; no allocation) ----------------
// float scratch layout (element offsets)
#define OF_H1    0          // BN*128
#define OF_X1    4194304    // BN*128
#define OF_H2    8388608    // BN*64
#define OF_X2    10485760   // BN*64
#define OF_H3    12582912   // BN*64
#define OF_X3    14680064   // BN*16
#define OF_AS1   15204352   // BN*4
#define OF_AD1   15335424
#define OF_AS2   15466496
#define OF_AD2   15597568
#define OF_AS3   15728640
#define OF_AD3   15859712
#define OF_MIXIN 15990784   // BN*16
#define OF_CAT   16515072   // 256*2080
#define OF_MIX   17047552   // 256*512
#define OF_D2    17178624
#define OF_D3A   17309696
#define OF_D3B   17440768
#define F_TOTAL  17571840

__device__ float g_f[F_TOTAL];
// int scratch: deg[BN], off[BN], cur[BN], ssrc[NE]
__device__ int   g_i[3 * BNh + NEh];

// ---------------- CSR build ----------------
__global__ void k_hist(const int* __restrict__ dst, int* __restrict__ deg) {
    int e = blockIdx.x * blockDim.x + threadIdx.x;
    if (e < NEh) atomicAdd(&deg[dst[e]], 1);
}

__global__ void k_scan(const int* __restrict__ deg, int* __restrict__ off) {
    __shared__ int part[1024];
    int t = threadIdx.x;
    int base = t * 32;
    int loc[32];
    int s = 0;
#pragma unroll
    for (int i = 0; i < 32; i++) { loc[i] = deg[base + i]; s += loc[i]; }
    part[t] = s;
    __syncthreads();
    for (int o = 1; o < 1024; o <<= 1) {
        int v = (t >= o) ? part[t - o] : 0;
        __syncthreads();
        part[t] += v;
        __syncthreads();
    }
    int pre = (t == 0) ? 0 : part[t - 1];
#pragma unroll
    for (int i = 0; i < 32; i++) { off[base + i] = pre; pre += loc[i]; }
}

__global__ void k_scatter(const int* __restrict__ src, const int* __restrict__ dst,
                          const int* __restrict__ off, int* __restrict__ cur,
                          int* __restrict__ ssrc) {
    int e = blockIdx.x * blockDim.x + threadIdx.x;
    if (e < NEh) {
        int d = dst[e];
        int p = atomicAdd(&cur[d], 1);
        ssrc[off[d] + p] = src[e];
    }
}

// ---------------- GAT layer 1: projection + attention coefficients ----------------
// h1 = X(BN,8) @ W(128,8)^T ; asrc/adst per (node, head)
__global__ void k_h1(const float* __restrict__ X, const float* __restrict__ W,
                     const float* __restrict__ asr, const float* __restrict__ ads,
                     float* __restrict__ h1, float* __restrict__ as1, float* __restrict__ ad1) {
    int warp = threadIdx.x >> 5, lane = threadIdx.x & 31;
    int n = blockIdx.x * 8 + warp;
    float xr[8];
#pragma unroll
    for (int k = 0; k < 8; k++) xr[k] = X[n * 8 + k];
    float hv[4];
#pragma unroll
    for (int j = 0; j < 4; j++) {
        int f = j * 32 + lane;
        float s = 0.f;
#pragma unroll
        for (int k = 0; k < 8; k++) s += xr[k] * W[f * 8 + k];
        hv[j] = s;
        h1[n * 128 + f] = s;
    }
#pragma unroll
    for (int j = 0; j < 4; j++) {
        float pa = hv[j] * asr[j * 32 + lane];
        float pd = hv[j] * ads[j * 32 + lane];
#pragma unroll
        for (int o = 16; o > 0; o >>= 1) {
            pa += __shfl_xor_sync(0xffffffffu, pa, o);
            pd += __shfl_xor_sync(0xffffffffu, pd, o);
        }
        if (lane == 0) { as1[n * 4 + j] = pa; ad1[n * 4 + j] = pd; }
    }
}

// attention coefficients for layers 2/3 (h: [BN, 4, 16])
__global__ void k_attn(const float* __restrict__ h, const float* __restrict__ asr,
                       const float* __restrict__ ads, float* __restrict__ as_,
                       float* __restrict__ ad_) {
    int id = blockIdx.x * blockDim.x + threadIdx.x;  // BN*4
    int n = id >> 2, hh = id & 3;
    const float* hp = h + n * 64 + hh * 16;
    const float* ap = asr + hh * 16;
    const float* dp = ads + hh * 16;
    float sa = 0.f, sd = 0.f;
#pragma unroll
    for (int c = 0; c < 16; c++) { float v = hp[c]; sa += v * ap[c]; sd += v * dp[c]; }
    as_[id] = sa;
    ad_[id] = sd;
}

__device__ __forceinline__ float leaky(float v) { return v > 0.f ? v : 0.2f * v; }

// ---------------- edge softmax + aggregation: one warp per dst node ----------------
// MODE 0: Cout/head=32, concat, relu   (layer 1)
// MODE 1: Cout/head=16, concat, relu   (layer 2)
// MODE 2: Cout/head=16, head-mean, relu (layer 3)
template <int MODE>
__global__ void k_agg(const int* __restrict__ off, const int* __restrict__ deg,
                      const int* __restrict__ ssrc, const float* __restrict__ as_,
                      const float* __restrict__ ad_, const float* __restrict__ h,
                      float* __restrict__ out) {
    int warp = threadIdx.x >> 5, lane = threadIdx.x & 31;
    int n = blockIdx.x * 8 + warp;
    int o0 = off[n], dg = deg[n];
    if (dg == 0) {
        if (MODE == 0) {
#pragma unroll
            for (int j = 0; j < 4; j++) out[n * 128 + j * 32 + lane] = 0.f;
        } else if (MODE == 1) {
            out[n * 64 + lane] = 0.f;
            out[n * 64 + 32 + lane] = 0.f;
        } else {
            if (lane < 16) out[n * 16 + lane] = 0.f;
        }
        return;
    }
    float adn[4];
#pragma unroll
    for (int j = 0; j < 4; j++) adn[j] = ad_[n * 4 + j];

    // phase 1: per-head max over incoming edges
    float mh[4] = {-1e30f, -1e30f, -1e30f, -1e30f};
    for (int e = lane; e < dg; e += 32) {
        int s = ssrc[o0 + e];
#pragma unroll
        for (int j = 0; j < 4; j++)
            mh[j] = fmaxf(mh[j], leaky(as_[s * 4 + j] + adn[j]));
    }
#pragma unroll
    for (int j = 0; j < 4; j++)
#pragma unroll
        for (int o = 16; o > 0; o >>= 1)
            mh[j] = fmaxf(mh[j], __shfl_xor_sync(0xffffffffu, mh[j], o));

    // phase 2: per-head denominator
    float dh[4] = {0.f, 0.f, 0.f, 0.f};
    for (int e = lane; e < dg; e += 32) {
        int s = ssrc[o0 + e];
#pragma unroll
        for (int j = 0; j < 4; j++)
            dh[j] += __expf(leaky(as_[s * 4 + j] + adn[j]) - mh[j]);
    }
#pragma unroll
    for (int j = 0; j < 4; j++) {
#pragma unroll
        for (int o = 16; o > 0; o >>= 1)
            dh[j] += __shfl_xor_sync(0xffffffffu, dh[j], o);
        dh[j] = 1.f / (dh[j] + 1e-16f);
    }

    // phase 3: weighted aggregation (all lanes walk edges together)
    if (MODE == 0) {
        float acc[4] = {0.f, 0.f, 0.f, 0.f};
        for (int e = 0; e < dg; e++) {
            int s = ssrc[o0 + e];
            float al[4];
#pragma unroll
            for (int j = 0; j < 4; j++)
                al[j] = __expf(leaky(as_[s * 4 + j] + adn[j]) - mh[j]) * dh[j];
#pragma unroll
            for (int j = 0; j < 4; j++)
                acc[j] += al[j] * h[s * 128 + j * 32 + lane];
        }
#pragma unroll
        for (int j = 0; j < 4; j++) out[n * 128 + j * 32 + lane] = fmaxf(acc[j], 0.f);
    } else {
        int h0 = lane >> 4;        // head of feature `lane`
        int h1b = 2 + (lane >> 4); // head of feature `lane+32`
        float a0 = 0.f, a1 = 0.f;
        for (int e = 0; e < dg; e++) {
            int s = ssrc[o0 + e];
            float al[4];
#pragma unroll
            for (int j = 0; j < 4; j++)
                al[j] = __expf(leaky(as_[s * 4 + j] + adn[j]) - mh[j]) * dh[j];
            a0 += al[h0] * h[s * 64 + lane];
            a1 += al[h1b] * h[s * 64 + 32 + lane];
        }
        if (MODE == 1) {
            out[n * 64 + lane] = fmaxf(a0, 0.f);
            out[n * 64 + 32 + lane] = fmaxf(a1, 0.f);
        } else {
            float t = a0 + a1;
            t += __shfl_xor_sync(0xffffffffu, t, 16);
            if (lane < 16) out[n * 16 + lane] = fmaxf(0.25f * t, 0.f);
        }
    }
}

// ---------------- mixin: relu(boxes@Wb^T+bb) + relu(labels@Wl^T+bl) ----------------
__global__ void k_mixin(const float* __restrict__ X, const float* __restrict__ Wb,
                        const float* __restrict__ bb, const float* __restrict__ Wl,
                        const float* __restrict__ bl, float* __restrict__ mixin) {
    int id = blockIdx.x * blockDim.x + threadIdx.x;  // BN*16
    int n = id >> 4, j = id & 15;
    float sb = bb[j];
#pragma unroll
    for (int c = 0; c < 7; c++) sb += X[n * 8 + 1 + c] * Wb[j * 7 + c];
    float sl = X[n * 8] * Wl[j] + bl[j];
    mixin[id] = fmaxf(sb, 0.f) + fmaxf(sl, 0.f);
}

// ---------------- concat [class_labels | x3-rows] ----------------
__global__ void k_cat(const float* __restrict__ cl, const float* __restrict__ x3,
                      float* __restrict__ cat) {
    int id = blockIdx.x * blockDim.x + threadIdx.x;
    if (id < 256 * 2080) {
        int b = id / 2080, c = id % 2080;
        cat[id] = (c < 32) ? cl[b * 32 + c] : x3[b * 2048 + (c - 32)];
    }
}

// ---------------- generic SGEMM: C = act(A(MxK) @ W(NxK)^T + bias) [+ addend] ----------------
// 64x64 tile, BK=16, 256 threads, 4x4 micro-tile. M,N multiples of 64; K multiple of 16.
__global__ void k_sgemm(const float* __restrict__ A, const float* __restrict__ W,
                        const float* __restrict__ bias, const float* __restrict__ addend,
                        float* __restrict__ C, int M, int N, int K, int doRelu) {
    __shared__ float As[16][64];
    __shared__ float Ws[16][64];
    int t = threadIdx.x;
    int tx = t & 15, ty = t >> 4;
    int m0 = blockIdx.y * 64, n0 = blockIdx.x * 64;
    int lm = t >> 2;
    int lk4 = (t & 3) * 4;
    const float* Ag = A + (size_t)(m0 + lm) * K + lk4;
    const float* Wg = W + (size_t)(n0 + lm) * K + lk4;
    float acc[4][4] = {};
    for (int k0 = 0; k0 < K; k0 += 16) {
        float4 av = *(const float4*)(Ag + k0);
        float4 wv = *(const float4*)(Wg + k0);
        As[lk4 + 0][lm] = av.x; As[lk4 + 1][lm] = av.y;
        As[lk4 + 2][lm] = av.z; As[lk4 + 3][lm] = av.w;
        Ws[lk4 + 0][lm] = wv.x; Ws[lk4 + 1][lm] = wv.y;
        Ws[lk4 + 2][lm] = wv.z; Ws[lk4 + 3][lm] = wv.w;
        __syncthreads();
#pragma unroll
        for (int k = 0; k < 16; k++) {
            float4 a = *(const float4*)&As[k][ty * 4];
            float4 w = *(const float4*)&Ws[k][tx * 4];
            acc[0][0] += a.x * w.x; acc[0][1] += a.x * w.y; acc[0][2] += a.x * w.z; acc[0][3] += a.x * w.w;
            acc[1][0] += a.y * w.x; acc[1][1] += a.y * w.y; acc[1][2] += a.y * w.z; acc[1][3] += a.y * w.w;
            acc[2][0] += a.z * w.x; acc[2][1] += a.z * w.y; acc[2][2] += a.z * w.z; acc[2][3] += a.z * w.w;
            acc[3][0] += a.w * w.x; acc[3][1] += a.w * w.y; acc[3][2] += a.w * w.z; acc[3][3] += a.w * w.w;
        }
        __syncthreads();
    }
#pragma unroll
    for (int i = 0; i < 4; i++) {
        int m = m0 + ty * 4 + i;
#pragma unroll
        for (int j = 0; j < 4; j++) {
            int n = n0 + tx * 4 + j;
            float v = acc[i][j];
            if (bias) v += bias[n];
            if (doRelu) v = fmaxf(v, 0.f);
            if (addend) v += addend[(size_t)m * N + n];
            C[(size_t)m * N + n] = v;
        }
    }
}

// ---------------- launch ----------------
extern "C" void kernel_launch(void* const* d_in, const int* in_sizes, int n_in,
                              void* d_out, int out_size) {
    const int*   E    = (const int*)d_in[0];
    const float* X    = (const float*)d_in[1];
    const float* cl   = (const float*)d_in[2];
    const float* g1W  = (const float*)d_in[3];
    const float* g1as = (const float*)d_in[4];
    const float* g1ad = (const float*)d_in[5];
    const float* g2W  = (const float*)d_in[6];
    const float* g2as = (const float*)d_in[7];
    const float* g2ad = (const float*)d_in[8];
    const float* g3W  = (const float*)d_in[9];
    const float* g3as = (const float*)d_in[10];
    const float* g3ad = (const float*)d_in[11];
    const float* Wb   = (const float*)d_in[12];
    const float* bb   = (const float*)d_in[13];
    const float* Wl   = (const float*)d_in[14];
    const float* bl   = (const float*)d_in[15];
    const float* W1   = (const float*)d_in[16];
    const float* b1   = (const float*)d_in[17];
    const float* W2   = (const float*)d_in[18];
    const float* b2   = (const float*)d_in[19];
    const float* W3   = (const float*)d_in[20];
    const float* b3   = (const float*)d_in[21];
    const float* Wm   = (const float*)d_in[22];
    const float* bm   = (const float*)d_in[23];
    const float* Wv   = (const float*)d_in[24];
    const float* bv   = (const float*)d_in[25];

    float* fb; cudaGetSymbolAddress((void**)&fb, g_f);
    int*   ib; cudaGetSymbolAddress((void**)&ib, g_i);

    int* deg  = ib;
    int* off  = ib + BNh;
    int* cur  = ib + 2 * BNh;
    int* ssrc = ib + 3 * BNh;

    float* h1    = fb + OF_H1;
    float* x1    = fb + OF_X1;
    float* h2    = fb + OF_H2;
    float* x2    = fb + OF_X2;
    float* h3    = fb + OF_H3;
    float* x3    = fb + OF_X3;
    float* as1   = fb + OF_AS1;
    float* ad1   = fb + OF_AD1;
    float* as2   = fb + OF_AS2;
    float* ad2   = fb + OF_AD2;
    float* as3   = fb + OF_AS3;
    float* ad3   = fb + OF_AD3;
    float* mixin = fb + OF_MIXIN;
    float* cat   = fb + OF_CAT;
    float* mixv  = fb + OF_MIX;
    float* d2b   = fb + OF_D2;
    float* d3a   = fb + OF_D3A;
    float* d3b   = fb + OF_D3B;

    const int* src = E;
    const int* dst = E + NEh;

    // CSR build
    cudaMemsetAsync(deg, 0, BNh * sizeof(int));
    cudaMemsetAsync(cur, 0, BNh * sizeof(int));
    k_hist<<<NEh / 256, 256>>>(dst, deg);
    k_scan<<<1, 1024>>>(deg, off);
    k_scatter<<<NEh / 256, 256>>>(src, dst, off, cur, ssrc);

    // GAT layer 1
    k_h1<<<BNh / 8, 256>>>(X, g1W, g1as, g1ad, h1, as1, ad1);
    k_agg<0><<<BNh / 8, 256>>>(off, deg, ssrc, as1, ad1, h1, x1);

    // GAT layer 2
    k_sgemm<<<dim3(1, BNh / 64), 256>>>(x1, g2W, nullptr, nullptr, h2, BNh, 64, 128, 0);
    k_attn<<<(BNh * 4) / 256, 256>>>(h2, g2as, g2ad, as2, ad2);
    k_agg<1><<<BNh / 8, 256>>>(off, deg, ssrc, as2, ad2, h2, x2);

    // GAT layer 3 (head mean)
    k_sgemm<<<dim3(1, BNh / 64), 256>>>(x2, g3W, nullptr, nullptr, h3, BNh, 64, 64, 0);
    k_attn<<<(BNh * 4) / 256, 256>>>(h3, g3as, g3ad, as3, ad3);
    k_agg<2><<<BNh / 8, 256>>>(off, deg, ssrc, as3, ad3, h3, x3);

    // dense tail
    k_mixin<<<(BNh * 16) / 256, 256>>>(X, Wb, bb, Wl, bl, mixin);
    k_sgemm<<<dim3(8, 4), 256>>>(mixin, W1, b1, nullptr, mixv, 256, 512, 2048, 1);
    k_cat<<<(256 * 2080 + 255) / 256, 256>>>(cl, x3, cat);
    k_sgemm<<<dim3(8, 4), 256>>>(cat, W2, b2, mixv, d2b, 256, 512, 2080, 1);
    k_sgemm<<<dim3(8, 4), 256>>>(d2b, W3, b3, nullptr, d3a, 256, 512, 512, 1);
    k_sgemm<<<dim3(8, 4), 256>>>(d3a, W3, b3, nullptr, d3b, 256, 512, 512, 1);

    float* out = (float*)d_out;
    k_sgemm<<<dim3(2, 4), 256>>>(d3b, Wm, bm, nullptr, out, 256, 128, 512, 0);
    k_sgemm<<<dim3(2, 4), 256>>>(d3b, Wv, bv, nullptr, out + 256 * 128, 256, 128, 512, 0);
}

// round 3
// speedup vs baseline: 1.0021x; 1.0021x over previous
#include <cuda_runtime.h>

#define Bh  256
#define Nh  128
#define BNh 32768
#define NEh 524288
#define Fh  8
#define Hh  4
#define H1h 32
#define H2h 16
#define H3h 512
#define LATh 128
#define Ch  32

// ---------------- scratch (static device globals; no allocation) ----------------
// float scratch layout (element offsets)
#define OF_H1    0          // BN*128
#define OF_X1    4194304    // BN*128
#define OF_H2    8388608    // BN*64
#define OF_X2    10485760   // BN*64
#define OF_H3    12582912   // BN*64
#define OF_X3    14680064   // BN*16
#define OF_AS1   15204352   // BN*4
#define OF_AD1   15335424
#define OF_AS2   15466496
#define OF_AD2   15597568
#define OF_AS3   15728640
#define OF_AD3   15859712
#define OF_MIXIN 15990784   // BN*16
#define OF_CAT   16515072   // 256*2080
#define OF_MIX   17047552   // 256*512
#define OF_D2    17178624
#define OF_D3A   17309696
#define OF_D3B   17440768
#define F_TOTAL  17571840

__device__ float g_f[F_TOTAL];
// int scratch: deg[BN], off[BN], cur[BN], ssrc[NE]
__device__ int   g_i[3 * BNh + NEh];

// ---------------- CSR build ----------------
__global__ void k_hist(const int* __restrict__ dst, int* __restrict__ deg) {
    int e = blockIdx.x * blockDim.x + threadIdx.x;
    if (e < NEh) atomicAdd(&deg[dst[e]], 1);
}

__global__ void k_scan(const int* __restrict__ deg, int* __restrict__ off) {
    __shared__ int part[1024];
    int t = threadIdx.x;
    int base = t * 32;
    int loc[32];
    int s = 0;
#pragma unroll
    for (int i = 0; i < 32; i++) { loc[i] = deg[base + i]; s += loc[i]; }
    part[t] = s;
    __syncthreads();
    for (int o = 1; o < 1024; o <<= 1) {
        int v = (t >= o) ? part[t - o] : 0;
        __syncthreads();
        part[t] += v;
        __syncthreads();
    }
    int pre = (t == 0) ? 0 : part[t - 1];
#pragma unroll
    for (int i = 0; i < 32; i++) { off[base + i] = pre; pre += loc[i]; }
}

__global__ void k_scatter(const int* __restrict__ src, const int* __restrict__ dst,
                          const int* __restrict__ off, int* __restrict__ cur,
                          int* __restrict__ ssrc) {
    int e = blockIdx.x * blockDim.x + threadIdx.x;
    if (e < NEh) {
        int d = dst[e];
        int p = atomicAdd(&cur[d], 1);
        ssrc[off[d] + p] = src[e];
    }
}

// ---------------- GAT layer 1: projection + attention coefficients ----------------
// h1 = X(BN,8) @ W(128,8)^T ; asrc/adst per (node, head)
__global__ void k_h1(const float* __restrict__ X, const float* __restrict__ W,
                     const float* __restrict__ asr, const float* __restrict__ ads,
                     float* __restrict__ h1, float* __restrict__ as1, float* __restrict__ ad1) {
    int warp = threadIdx.x >> 5, lane = threadIdx.x & 31;
    int n = blockIdx.x * 8 + warp;
    float xr[8];
#pragma unroll
    for (int k = 0; k < 8; k++) xr[k] = X[n * 8 + k];
    float hv[4];
#pragma unroll
    for (int j = 0; j < 4; j++) {
        int f = j * 32 + lane;
        float s = 0.f;
#pragma unroll
        for (int k = 0; k < 8; k++) s += xr[k] * W[f * 8 + k];
        hv[j] = s;
        h1[n * 128 + f] = s;
    }
#pragma unroll
    for (int j = 0; j < 4; j++) {
        float pa = hv[j] * asr[j * 32 + lane];
        float pd = hv[j] * ads[j * 32 + lane];
#pragma unroll
        for (int o = 16; o > 0; o >>= 1) {
            pa += __shfl_xor_sync(0xffffffffu, pa, o);
            pd += __shfl_xor_sync(0xffffffffu, pd, o);
        }
        if (lane == 0) { as1[n * 4 + j] = pa; ad1[n * 4 + j] = pd; }
    }
}

// attention coefficients for layers 2/3 (h: [BN, 4, 16])
__global__ void k_attn(const float* __restrict__ h, const float* __restrict__ asr,
                       const float* __restrict__ ads, float* __restrict__ as_,
                       float* __restrict__ ad_) {
    int id = blockIdx.x * blockDim.x + threadIdx.x;  // BN*4
    int n = id >> 2, hh = id & 3;
    const float* hp = h + n * 64 + hh * 16;
    const float* ap = asr + hh * 16;
    const float* dp = ads + hh * 16;
    float sa = 0.f, sd = 0.f;
#pragma unroll
    for (int c = 0; c < 16; c++) { float v = hp[c]; sa += v * ap[c]; sd += v * dp[c]; }
    as_[id] = sa;
    ad_[id] = sd;
}

__device__ __forceinline__ float leaky(float v) { return v > 0.f ? v : 0.2f * v; }

// ---------------- edge softmax + aggregation: one warp per dst node ----------------
// MODE 0: Cout/head=32, concat, relu   (layer 1)
// MODE 1: Cout/head=16, concat, relu   (layer 2)
// MODE 2: Cout/head=16, head-mean, relu (layer 3)
template <int MODE>
__global__ void k_agg(const int* __restrict__ off, const int* __restrict__ deg,
                      const int* __restrict__ ssrc, const float* __restrict__ as_,
                      const float* __restrict__ ad_, const float* __restrict__ h,
                      float* __restrict__ out) {
    int warp = threadIdx.x >> 5, lane = threadIdx.x & 31;
    int n = blockIdx.x * 8 + warp;
    int o0 = off[n], dg = deg[n];
    if (dg == 0) {
        if (MODE == 0) {
#pragma unroll
            for (int j = 0; j < 4; j++) out[n * 128 + j * 32 + lane] = 0.f;
        } else if (MODE == 1) {
            out[n * 64 + lane] = 0.f;
            out[n * 64 + 32 + lane] = 0.f;
        } else {
            if (lane < 16) out[n * 16 + lane] = 0.f;
        }
        return;
    }
    float adn[4];
#pragma unroll
    for (int j = 0; j < 4; j++) adn[j] = ad_[n * 4 + j];

    // phase 1: per-head max over incoming edges
    float mh[4] = {-1e30f, -1e30f, -1e30f, -1e30f};
    for (int e = lane; e < dg; e += 32) {
        int s = ssrc[o0 + e];
#pragma unroll
        for (int j = 0; j < 4; j++)
            mh[j] = fmaxf(mh[j], leaky(as_[s * 4 + j] + adn[j]));
    }
#pragma unroll
    for (int j = 0; j < 4; j++)
#pragma unroll
        for (int o = 16; o > 0; o >>= 1)
            mh[j] = fmaxf(mh[j], __shfl_xor_sync(0xffffffffu, mh[j], o));

    // phase 2: per-head denominator
    float dh[4] = {0.f, 0.f, 0.f, 0.f};
    for (int e = lane; e < dg; e += 32) {
        int s = ssrc[o0 + e];
#pragma unroll
        for (int j = 0; j < 4; j++)
            dh[j] += __expf(leaky(as_[s * 4 + j] + adn[j]) - mh[j]);
    }
#pragma unroll
    for (int j = 0; j < 4; j++) {
#pragma unroll
        for (int o = 16; o > 0; o >>= 1)
            dh[j] += __shfl_xor_sync(0xffffffffu, dh[j], o);
        dh[j] = 1.f / (dh[j] + 1e-16f);
    }

    // phase 3: weighted aggregation (all lanes walk edges together)
    if (MODE == 0) {
        float acc[4] = {0.f, 0.f, 0.f, 0.f};
        for (int e = 0; e < dg; e++) {
            int s = ssrc[o0 + e];
            float al[4];
#pragma unroll
            for (int j = 0; j < 4; j++)
                al[j] = __expf(leaky(as_[s * 4 + j] + adn[j]) - mh[j]) * dh[j];
#pragma unroll
            for (int j = 0; j < 4; j++)
                acc[j] += al[j] * h[s * 128 + j * 32 + lane];
        }
#pragma unroll
        for (int j = 0; j < 4; j++) out[n * 128 + j * 32 + lane] = fmaxf(acc[j], 0.f);
    } else {
        int h0 = lane >> 4;        // head of feature `lane`
        int h1b = 2 + (lane >> 4); // head of feature `lane+32`
        float a0 = 0.f, a1 = 0.f;
        for (int e = 0; e < dg; e++) {
            int s = ssrc[o0 + e];
            float al[4];
#pragma unroll
            for (int j = 0; j < 4; j++)
                al[j] = __expf(leaky(as_[s * 4 + j] + adn[j]) - mh[j]) * dh[j];
            a0 += al[h0] * h[s * 64 + lane];
            a1 += al[h1b] * h[s * 64 + 32 + lane];
        }
        if (MODE == 1) {
            out[n * 64 + lane] = fmaxf(a0, 0.f);
            out[n * 64 + 32 + lane] = fmaxf(a1, 0.f);
        } else {
            float t = a0 + a1;
            t += __shfl_xor_sync(0xffffffffu, t, 16);
            if (lane < 16) out[n * 16 + lane] = fmaxf(0.25f * t, 0.f);
        }
    }
}

// ---------------- mixin: relu(boxes@Wb^T+bb) + relu(labels@Wl^T+bl) ----------------
__global__ void k_mixin(const float* __restrict__ X, const float* __restrict__ Wb,
                        const float* __restrict__ bb, const float* __restrict__ Wl,
                        const float* __restrict__ bl, float* __restrict__ mixin) {
    int id = blockIdx.x * blockDim.x + threadIdx.x;  // BN*16
    int n = id >> 4, j = id & 15;
    float sb = bb[j];
#pragma unroll
    for (int c = 0; c < 7; c++) sb += X[n * 8 + 1 + c] * Wb[j * 7 + c];
    float sl = X[n * 8] * Wl[j] + bl[j];
    mixin[id] = fmaxf(sb, 0.f) + fmaxf(sl, 0.f);
}

// ---------------- concat [class_labels | x3-rows] ----------------
__global__ void k_cat(const float* __restrict__ cl, const float* __restrict__ x3,
                      float* __restrict__ cat) {
    int id = blockIdx.x * blockDim.x + threadIdx.x;
    if (id < 256 * 2080) {
        int b = id / 2080, c = id % 2080;
        cat[id] = (c < 32) ? cl[b * 32 + c] : x3[b * 2048 + (c - 32)];
    }
}

// ---------------- generic SGEMM: C = act(A(MxK) @ W(NxK)^T + bias) [+ addend] ----------------
// 64x64 tile, BK=16, 256 threads, 4x4 micro-tile. M,N multiples of 64; K multiple of 16.
__global__ void k_sgemm(const float* __restrict__ A, const float* __restrict__ W,
                        const float* __restrict__ bias, const float* __restrict__ addend,
                        float* __restrict__ C, int M, int N, int K, int doRelu) {
    __shared__ float As[16][64];
    __shared__ float Ws[16][64];
    int t = threadIdx.x;
    int tx = t & 15, ty = t >> 4;
    int m0 = blockIdx.y * 64, n0 = blockIdx.x * 64;
    int lm = t >> 2;
    int lk4 = (t & 3) * 4;
    const float* Ag = A + (size_t)(m0 + lm) * K + lk4;
    const float* Wg = W + (size_t)(n0 + lm) * K + lk4;
    float acc[4][4] = {};
    for (int k0 = 0; k0 < K; k0 += 16) {
        float4 av = *(const float4*)(Ag + k0);
        float4 wv = *(const float4*)(Wg + k0);
        As[lk4 + 0][lm] = av.x; As[lk4 + 1][lm] = av.y;
        As[lk4 + 2][lm] = av.z; As[lk4 + 3][lm] = av.w;
        Ws[lk4 + 0][lm] = wv.x; Ws[lk4 + 1][lm] = wv.y;
        Ws[lk4 + 2][lm] = wv.z; Ws[lk4 + 3][lm] = wv.w;
        __syncthreads();
#pragma unroll
        for (int k = 0; k < 16; k++) {
            float4 a = *(const float4*)&As[k][ty * 4];
            float4 w = *(const float4*)&Ws[k][tx * 4];
            acc[0][0] += a.x * w.x; acc[0][1] += a.x * w.y; acc[0][2] += a.x * w.z; acc[0][3] += a.x * w.w;
            acc[1][0] += a.y * w.x; acc[1][1] += a.y * w.y; acc[1][2] += a.y * w.z; acc[1][3] += a.y * w.w;
            acc[2][0] += a.z * w.x; acc[2][1] += a.z * w.y; acc[2][2] += a.z * w.z; acc[2][3] += a.z * w.w;
            acc[3][0] += a.w * w.x; acc[3][1] += a.w * w.y; acc[3][2] += a.w * w.z; acc[3][3] += a.w * w.w;
        }
        __syncthreads();
    }
#pragma unroll
    for (int i = 0; i < 4; i++) {
        int m = m0 + ty * 4 + i;
#pragma unroll
        for (int j = 0; j < 4; j++) {
            int n = n0 + tx * 4 + j;
            float v = acc[i][j];
            if (bias) v += bias[n];
            if (doRelu) v = fmaxf(v, 0.f);
            if (addend) v += addend[(size_t)m * N + n];
            C[(size_t)m * N + n] = v;
        }
    }
}

// ---------------- launch ----------------
extern "C" void kernel_launch(void* const* d_in, const int* in_sizes, int n_in,
                              void* d_out, int out_size) {
    const int*   E    = (const int*)d_in[0];
    const float* X    = (const float*)d_in[1];
    const float* cl   = (const float*)d_in[2];
    const float* g1W  = (const float*)d_in[3];
    const float* g1as = (const float*)d_in[4];
    const float* g1ad = (const float*)d_in[5];
    const float* g2W  = (const float*)d_in[6];
    const float* g2as = (const float*)d_in[7];
    const float* g2ad = (const float*)d_in[8];
    const float* g3W  = (const float*)d_in[9];
    const float* g3as = (const float*)d_in[10];
    const float* g3ad = (const float*)d_in[11];
    const float* Wb   = (const float*)d_in[12];
    const float* bb   = (const float*)d_in[13];
    const float* Wl   = (const float*)d_in[14];
    const float* bl   = (const float*)d_in[15];
    const float* W1   = (const float*)d_in[16];
    const float* b1   = (const float*)d_in[17];
    const float* W2   = (const float*)d_in[18];
    const float* b2   = (const float*)d_in[19];
    const float* W3   = (const float*)d_in[20];
    const float* b3   = (const float*)d_in[21];
    const float* Wm   = (const float*)d_in[22];
    const float* bm   = (const float*)d_in[23];
    const float* Wv   = (const float*)d_in[24];
    const float* bv   = (const float*)d_in[25];

    float* fb; cudaGetSymbolAddress((void**)&fb, g_f);
    int*   ib; cudaGetSymbolAddress((void**)&ib, g_i);

    int* deg  = ib;
    int* off  = ib + BNh;
    int* cur  = ib + 2 * BNh;
    int* ssrc = ib + 3 * BNh;

    float* h1    = fb + OF_H1;
    float* x1    = fb + OF_X1;
    float* h2    = fb + OF_H2;
    float* x2    = fb + OF_X2;
    float* h3    = fb + OF_H3;
    float* x3    = fb + OF_X3;
    float* as1   = fb + OF_AS1;
    float* ad1   = fb + OF_AD1;
    float* as2   = fb + OF_AS2;
    float* ad2   = fb + OF_AD2;
    float* as3   = fb + OF_AS3;
    float* ad3   = fb + OF_AD3;
    float* mixin = fb + OF_MIXIN;
    float* cat   = fb + OF_CAT;
    float* mixv  = fb + OF_MIX;
    float* d2b   = fb + OF_D2;
    float* d3a   = fb + OF_D3A;
    float* d3b   = fb + OF_D3B;

    const int* src = E;
    const int* dst = E + NEh;

    // CSR build
    cudaMemsetAsync(deg, 0, BNh * sizeof(int));
    cudaMemsetAsync(cur, 0, BNh * sizeof(int));
    k_hist<<<NEh / 256, 256>>>(dst, deg);
    k_scan<<<1, 1024>>>(deg, off);
    k_scatter<<<NEh / 256, 256>>>(src, dst, off, cur, ssrc);

    // GAT layer 1
    k_h1<<<BNh / 8, 256>>>(X, g1W, g1as, g1ad, h1, as1, ad1);
    k_agg<0><<<BNh / 8, 256>>>(off, deg, ssrc, as1, ad1, h1, x1);

    // GAT layer 2
    k_sgemm<<<dim3(1, BNh / 64), 256>>>(x1, g2W, nullptr, nullptr, h2, BNh, 64, 128, 0);
    k_attn<<<(BNh * 4) / 256, 256>>>(h2, g2as, g2ad, as2, ad2);
    k_agg<1><<<BNh / 8, 256>>>(off, deg, ssrc, as2, ad2, h2, x2);

    // GAT layer 3 (head mean)
    k_sgemm<<<dim3(1, BNh / 64), 256>>>(x2, g3W, nullptr, nullptr, h3, BNh, 64, 64, 0);
    k_attn<<<(BNh * 4) / 256, 256>>>(h3, g3as, g3ad, as3, ad3);
    k_agg<2><<<BNh / 8, 256>>>(off, deg, ssrc, as3, ad3, h3, x3);

    // dense tail
    k_mixin<<<(BNh * 16) / 256, 256>>>(X, Wb, bb, Wl, bl, mixin);
    k_sgemm<<<dim3(8, 4), 256>>>(mixin, W1, b1, nullptr, mixv, 256, 512, 2048, 1);
    k_cat<<<(256 * 2080 + 255) / 256, 256>>>(cl, x3, cat);
    k_sgemm<<<dim3(8, 4), 256>>>(cat, W2, b2, mixv, d2b, 256, 512, 2080, 1);
    k_sgemm<<<dim3(8, 4), 256>>>(d2b, W3, b3, nullptr, d3a, 256, 512, 512, 1);
    k_sgemm<<<dim3(8, 4), 256>>>(d3a, W3, b3, nullptr, d3b, 256, 512, 512, 1);

    float* out = (float*)d_out;
    k_sgemm<<<dim3(2, 4), 256>>>(d3b, Wm, bm, nullptr, out, 256, 128, 512, 0);
    k_sgemm<<<dim3(2, 4), 256>>>(d3b, Wv, bv, nullptr, out + 256 * 128, 256, 128, 512, 0);
}